// round 1
// baseline (speedup 1.0000x reference)
#include <cuda_runtime.h>
#include <cstdint>

// Problem constants
#define Bb 2
#define Tt 4096
#define Dd 4096
#define Hh 32
#define HKV 8
#define DH 128
#define Mrows 8192         // B*T
#define Ncols 6144         // D + 2*HKV*DH
#define Kdim 4096

#define BM 128
#define BN 128
#define BK 32
#define AS_STRIDE 137      // A smem [k][m], padded: STS conflict-free, LDS <=2-way
#define BS_STRIDE 136      // B smem [k][n], padded: conflict-free, 16B-aligned rows

// Scratch: GEMM result C[8192][6144]  (~201 MB, bss-style device global)
__device__ float g_C[(size_t)Mrows * Ncols];
// RoPE table: [t][j] -> (cos, sin), j = 0..63
__device__ float2 g_tab[Tt * (DH / 2)];

__device__ __forceinline__ uint32_t f2tf32(float f) {
    uint32_t u;
    asm("cvt.rna.tf32.f32 %0, %1;" : "=r"(u) : "f"(f));
    return u;
}

__device__ __forceinline__ void mma_tf32(float c[4], const uint32_t a[4], const uint32_t b[2]) {
    asm volatile(
        "mma.sync.aligned.m16n8k8.row.col.f32.tf32.tf32.f32 "
        "{%0,%1,%2,%3}, {%4,%5,%6,%7}, {%8,%9}, {%0,%1,%2,%3};"
        : "+f"(c[0]), "+f"(c[1]), "+f"(c[2]), "+f"(c[3])
        : "r"(a[0]), "r"(a[1]), "r"(a[2]), "r"(a[3]), "r"(b[0]), "r"(b[1]));
}

// ---------------------------------------------------------------------------
// Kernel 1: RoPE cos/sin table (fp64 internally; tiny)
// ---------------------------------------------------------------------------
__global__ void rope_table_kernel() {
    int idx = blockIdx.x * blockDim.x + threadIdx.x;
    if (idx >= Tt * 64) return;
    int t = idx >> 6;
    int j = idx & 63;
    double inv = pow(10000.0, -((double)(2 * j)) / (double)DH);
    double a = (double)t * inv;
    double s, c;
    sincos(a, &s, &c);
    g_tab[idx] = make_float2((float)c, (float)s);
}

// ---------------------------------------------------------------------------
// Kernel 2: tf32 GEMM  C = x @ [Wq | Wk | Wv]
// Grid: 3072 blocks (64 M-tiles x 48 N-tiles), GROUP_M=16 swizzle for L2 reuse
// Block: 256 threads = 8 warps (2 M x 4 N), warp tile 64x32
// ---------------------------------------------------------------------------
__global__ __launch_bounds__(256, 2) void gemm_kernel(
    const float* __restrict__ x,
    const float* __restrict__ Wq,
    const float* __restrict__ Wk,
    const float* __restrict__ Wv)
{
    __shared__ float As[BK][AS_STRIDE];  // As[k][m]  (transposed stage)
    __shared__ float Bs[BK][BS_STRIDE]; // Bs[k][n]

    const int NT = 48;
    const int GM = 16;
    int gid = blockIdx.x;
    int per_group = GM * NT;
    int group = gid / per_group;
    int rem = gid % per_group;
    int mt = group * GM + (rem % GM);
    int nt = rem / GM;

    const float* W;
    int ldw, col0;
    if (nt < 32)      { W = Wq; ldw = 4096; col0 = nt * 128; }
    else if (nt < 40) { W = Wk; ldw = 1024; col0 = (nt - 32) * 128; }
    else              { W = Wv; ldw = 1024; col0 = (nt - 40) * 128; }

    const int m0 = mt * BM;
    const int tid = threadIdx.x;
    const int lane = tid & 31;
    const int wid = tid >> 5;
    const int warp_m = wid & 1;   // 0..1
    const int warp_n = wid >> 1;  // 0..3

    float acc[4][4][4];
    #pragma unroll
    for (int i = 0; i < 4; i++)
        #pragma unroll
        for (int j = 0; j < 4; j++)
            #pragma unroll
            for (int r = 0; r < 4; r++)
                acc[i][j][r] = 0.0f;

    #pragma unroll 1
    for (int k0 = 0; k0 < Kdim; k0 += BK) {
        // --- stage A tile (128 x 32), transposed into As[k][m], cvt to tf32 ---
        #pragma unroll
        for (int i = 0; i < 4; i++) {
            int idx = tid + i * 256;
            int row = idx >> 3;     // 0..127
            int kq = idx & 7;       // float4 index within k-row
            const float4 v = *reinterpret_cast<const float4*>(
                x + (size_t)(m0 + row) * Kdim + k0 + kq * 4);
            As[kq * 4 + 0][row] = __uint_as_float(f2tf32(v.x));
            As[kq * 4 + 1][row] = __uint_as_float(f2tf32(v.y));
            As[kq * 4 + 2][row] = __uint_as_float(f2tf32(v.z));
            As[kq * 4 + 3][row] = __uint_as_float(f2tf32(v.w));
        }
        // --- stage B tile (32 x 128) into Bs[k][n], cvt to tf32 ---
        #pragma unroll
        for (int i = 0; i < 4; i++) {
            int idx = tid + i * 256;
            int kr = idx >> 5;      // 0..31
            int nq = idx & 31;      // float4 index within n-row
            float4 v = *reinterpret_cast<const float4*>(
                W + (size_t)(k0 + kr) * ldw + col0 + nq * 4);
            v.x = __uint_as_float(f2tf32(v.x));
            v.y = __uint_as_float(f2tf32(v.y));
            v.z = __uint_as_float(f2tf32(v.z));
            v.w = __uint_as_float(f2tf32(v.w));
            *reinterpret_cast<float4*>(&Bs[kr][nq * 4]) = v;
        }
        __syncthreads();

        // --- compute: 4 k-steps of 8 ---
        #pragma unroll
        for (int ks = 0; ks < 4; ks++) {
            uint32_t a[4][4], b[4][2];
            const int kk = ks * 8 + (lane & 3);
            const int mrow = warp_m * 64 + (lane >> 2);
            #pragma unroll
            for (int mi = 0; mi < 4; mi++) {
                a[mi][0] = __float_as_uint(As[kk][mrow + mi * 16]);
                a[mi][1] = __float_as_uint(As[kk][mrow + mi * 16 + 8]);
                a[mi][2] = __float_as_uint(As[kk + 4][mrow + mi * 16]);
                a[mi][3] = __float_as_uint(As[kk + 4][mrow + mi * 16 + 8]);
            }
            const int ncol = warp_n * 32 + (lane >> 2);
            #pragma unroll
            for (int ni = 0; ni < 4; ni++) {
                b[ni][0] = __float_as_uint(Bs[kk][ncol + ni * 8]);
                b[ni][1] = __float_as_uint(Bs[kk + 4][ncol + ni * 8]);
            }
            #pragma unroll
            for (int mi = 0; mi < 4; mi++)
                #pragma unroll
                for (int ni = 0; ni < 4; ni++)
                    mma_tf32(acc[mi][ni], a[mi], b[ni]);
        }
        __syncthreads();
    }

    // --- write accumulators to scratch C ---
    const int nbase = nt * 128 + warp_n * 32;
    #pragma unroll
    for (int mi = 0; mi < 4; mi++) {
        int row = m0 + warp_m * 64 + mi * 16 + (lane >> 2);
        #pragma unroll
        for (int ni = 0; ni < 4; ni++) {
            int col = nbase + ni * 8 + (lane & 3) * 2;
            float* p = g_C + (size_t)row * Ncols + col;
            *reinterpret_cast<float2*>(p) = make_float2(acc[mi][ni][0], acc[mi][ni][1]);
            *reinterpret_cast<float2*>(p + (size_t)8 * Ncols) =
                make_float2(acc[mi][ni][2], acc[mi][ni][3]);
        }
    }
}

// ---------------------------------------------------------------------------
// Kernel 3: per-token epilogue — rmsnorm(q,k), gamma, RoPE, transpose, repeat
// One block per token (8192 blocks x 256 threads)
// Output layout: [q | k | v], each [B, H, T, DH] fp32
// ---------------------------------------------------------------------------
__global__ __launch_bounds__(256) void epilogue_kernel(
    const float* __restrict__ gq,
    const float* __restrict__ gk,
    float* __restrict__ out)
{
    const int bt = blockIdx.x;       // 0..8191
    const int b = bt >> 12;
    const int t = bt & 4095;
    const float* row = g_C + (size_t)bt * Ncols;
    const int tid = threadIdx.x;

    float2 qv[8], kv2[2];
    float4 vv;
    float ssq_q = 0.0f, ssq_k = 0.0f;
    #pragma unroll
    for (int i = 0; i < 8; i++) {
        int p = tid + i * 256;
        qv[i] = *reinterpret_cast<const float2*>(row + 2 * p);
        ssq_q += qv[i].x * qv[i].x + qv[i].y * qv[i].y;
    }
    #pragma unroll
    for (int i = 0; i < 2; i++) {
        int p = tid + i * 256;
        kv2[i] = *reinterpret_cast<const float2*>(row + 4096 + 2 * p);
        ssq_k += kv2[i].x * kv2[i].x + kv2[i].y * kv2[i].y;
    }
    vv = *reinterpret_cast<const float4*>(row + 5120 + tid * 4);

    __shared__ float redq[256], redk[256];
    redq[tid] = ssq_q;
    redk[tid] = ssq_k;
    __syncthreads();
    #pragma unroll
    for (int s = 128; s > 0; s >>= 1) {
        if (tid < s) {
            redq[tid] += redq[tid + s];
            redk[tid] += redk[tid + s];
        }
        __syncthreads();
    }
    const float rs_q = rsqrtf(redq[0] * (1.0f / 4096.0f) + 1e-5f);
    const float rs_k = rsqrtf(redk[0] * (1.0f / 1024.0f) + 1e-5f);

    const float2* tab = g_tab + t * 64;
    float* outq = out;
    float* outk = out + (size_t)33554432;  // B*H*T*DH
    float* outv = out + (size_t)67108864;

    // Q: rmsnorm + gamma + rope -> [b, h, t, :]
    #pragma unroll
    for (int i = 0; i < 8; i++) {
        int p = tid + i * 256;             // pair index 0..2047
        int h = p >> 6;
        int j = p & 63;
        float2 cs = tab[j];
        float x1 = qv[i].x * rs_q * gq[2 * p];
        float x2 = qv[i].y * rs_q * gq[2 * p + 1];
        float2 r = make_float2(x1 * cs.x - x2 * cs.y, x1 * cs.y + x2 * cs.x);
        *reinterpret_cast<float2*>(
            outq + (((size_t)(b * Hh + h) * Tt + t) * DH + 2 * j)) = r;
    }
    // K: rmsnorm + gamma + rope, repeated to 4 query heads
    #pragma unroll
    for (int i = 0; i < 2; i++) {
        int p = tid + i * 256;             // pair index 0..511
        int kh = p >> 6;
        int j = p & 63;
        float2 cs = tab[j];
        float x1 = kv2[i].x * rs_k * gk[2 * p];
        float x2 = kv2[i].y * rs_k * gk[2 * p + 1];
        float2 r = make_float2(x1 * cs.x - x2 * cs.y, x1 * cs.y + x2 * cs.x);
        #pragma unroll
        for (int rr = 0; rr < 4; rr++) {
            int h = kh * 4 + rr;
            *reinterpret_cast<float2*>(
                outk + (((size_t)(b * Hh + h) * Tt + t) * DH + 2 * j)) = r;
        }
    }
    // V: plain, repeated to 4 query heads
    {
        int d = (tid * 4) & 127;
        int kh = tid >> 5;
        #pragma unroll
        for (int rr = 0; rr < 4; rr++) {
            int h = kh * 4 + rr;
            *reinterpret_cast<float4*>(
                outv + (((size_t)(b * Hh + h) * Tt + t) * DH + d)) = vv;
        }
    }
}

// ---------------------------------------------------------------------------
extern "C" void kernel_launch(void* const* d_in, const int* in_sizes, int n_in,
                              void* d_out, int out_size)
{
    const float* x  = (const float*)d_in[0];
    const float* Wq = (const float*)d_in[1];
    const float* Wk = (const float*)d_in[2];
    const float* Wv = (const float*)d_in[3];
    const float* gq = (const float*)d_in[4];
    const float* gk = (const float*)d_in[5];
    float* out = (float*)d_out;

    rope_table_kernel<<<(Tt * 64 + 255) / 256, 256>>>();
    gemm_kernel<<<3072, 256>>>(x, Wq, Wk, Wv);
    epilogue_kernel<<<Mrows, 256>>>(gq, gk, out);
}

// round 2
// speedup vs baseline: 1.2988x; 1.2988x over previous
#include <cuda_runtime.h>
#include <cstdint>

// Problem constants
#define Bb 2
#define Tt 4096
#define Dd 4096
#define Hh 32
#define HKV 8
#define DH 128
#define Mrows 8192         // B*T
#define Ncols 6144         // D + 2*HKV*DH
#define Kdim 4096

#define BM 128
#define BN 128
#define BK 32
#define NKITER (Kdim / BK)   // 128
#define STAGES 3
#define ASTRIDE 36           // As[m][k] padded: frag LDS conflict-free, 16B rows
#define BSTRIDE 136          // Bs[k][n] padded: frag LDS conflict-free, 16B rows
#define A_STAGE_FLOATS (BM * ASTRIDE)   // 4608
#define B_STAGE_FLOATS (BK * BSTRIDE)   // 4352
#define SMEM_BYTES ((STAGES * (A_STAGE_FLOATS + B_STAGE_FLOATS)) * 4)  // 107520

// Scratch device globals
__device__ float g_C[(size_t)Mrows * Ncols];          // GEMM result (~201 MB)
__device__ float g_x[(size_t)Mrows * Kdim];           // tf32-converted x (~134 MB)
__device__ float g_W[(size_t)Kdim * Ncols];           // tf32-converted [Wq|Wk|Wv] (~100 MB)
__device__ float2 g_tab[Tt * (DH / 2)];               // RoPE (cos,sin) table

__device__ __forceinline__ uint32_t f2tf32(float f) {
    uint32_t u;
    asm("cvt.rna.tf32.f32 %0, %1;" : "=r"(u) : "f"(f));
    return u;
}

__device__ __forceinline__ void mma_tf32(float c[4], const uint32_t a[4], const uint32_t b[2]) {
    asm volatile(
        "mma.sync.aligned.m16n8k8.row.col.f32.tf32.tf32.f32 "
        "{%0,%1,%2,%3}, {%4,%5,%6,%7}, {%8,%9}, {%0,%1,%2,%3};"
        : "+f"(c[0]), "+f"(c[1]), "+f"(c[2]), "+f"(c[3])
        : "r"(a[0]), "r"(a[1]), "r"(a[2]), "r"(a[3]), "r"(b[0]), "r"(b[1]));
}

__device__ __forceinline__ void cp_async16(uint32_t smem_dst, const void* gsrc) {
    asm volatile("cp.async.cg.shared.global [%0], [%1], 16;\n"
                 :: "r"(smem_dst), "l"(gsrc));
}

// ---------------------------------------------------------------------------
// Kernel 1: RoPE cos/sin table (fp64 range-reduce, fp32 sincos)
// ---------------------------------------------------------------------------
__global__ void rope_table_kernel() {
    int idx = blockIdx.x * blockDim.x + threadIdx.x;
    if (idx >= Tt * 64) return;
    int t = idx >> 6;
    int j = idx & 63;
    // inv_freq = 10000^(-2j/128) = exp2(-2j/128 * log2(10000))
    double inv = exp2(-((double)(2 * j)) * (1.0 / 128.0) * 13.287712379549449);
    double a = (double)t * inv;
    double red = remainder(a, 6.283185307179586477);   // |red| <= pi
    float s, c;
    sincosf((float)red, &s, &c);
    g_tab[idx] = make_float2(c, s);
}

// ---------------------------------------------------------------------------
// Kernel 2a: convert x -> tf32 (float4 grid-stride)
// ---------------------------------------------------------------------------
__global__ void convert_x_kernel(const float* __restrict__ x) {
    size_t i = (size_t)blockIdx.x * blockDim.x + threadIdx.x;   // float4 index
    const size_t N4 = (size_t)Mrows * Kdim / 4;
    if (i >= N4) return;
    float4 v = reinterpret_cast<const float4*>(x)[i];
    v.x = __uint_as_float(f2tf32(v.x));
    v.y = __uint_as_float(f2tf32(v.y));
    v.z = __uint_as_float(f2tf32(v.z));
    v.w = __uint_as_float(f2tf32(v.w));
    reinterpret_cast<float4*>(g_x)[i] = v;
}

// ---------------------------------------------------------------------------
// Kernel 2b: convert + concat Wq|Wk|Wv -> tf32 g_W[k][0:6144]
// ---------------------------------------------------------------------------
__global__ void convert_w_kernel(const float* __restrict__ Wq,
                                 const float* __restrict__ Wk,
                                 const float* __restrict__ Wv) {
    size_t i = (size_t)blockIdx.x * blockDim.x + threadIdx.x;   // float4 index
    const size_t N4 = (size_t)Kdim * Ncols / 4;
    if (i >= N4) return;
    int c4 = (int)(i % (Ncols / 4));     // 0..1535
    size_t k = i / (Ncols / 4);
    int n = c4 * 4;
    float4 v;
    if (n < 4096)       v = *reinterpret_cast<const float4*>(Wq + k * 4096 + n);
    else if (n < 5120)  v = *reinterpret_cast<const float4*>(Wk + k * 1024 + (n - 4096));
    else                v = *reinterpret_cast<const float4*>(Wv + k * 1024 + (n - 5120));
    v.x = __uint_as_float(f2tf32(v.x));
    v.y = __uint_as_float(f2tf32(v.y));
    v.z = __uint_as_float(f2tf32(v.z));
    v.w = __uint_as_float(f2tf32(v.w));
    reinterpret_cast<float4*>(g_W)[i] = v;
}

// ---------------------------------------------------------------------------
// Kernel 3: tf32 GEMM with 3-stage cp.async pipeline
// C[8192,6144] = g_x[8192,4096] @ g_W[4096,6144]
// Grid: 3072 blocks (64 M x 48 N tiles, GROUP_M=16), 256 thr = 8 warps (2Mx4N)
// ---------------------------------------------------------------------------
__global__ __launch_bounds__(256, 2) void gemm_kernel() {
    extern __shared__ float smem[];
    float* As = smem;                              // STAGES * 4608
    float* Bs = smem + STAGES * A_STAGE_FLOATS;    // STAGES * 4352

    const int NT = 48;
    const int GM = 16;
    int gid = blockIdx.x;
    int per_group = GM * NT;
    int group = gid / per_group;
    int rem = gid % per_group;
    const int mt = group * GM + (rem % GM);
    const int nt = rem / GM;
    const int m0 = mt * BM;
    const int n0 = nt * BN;

    const int tid = threadIdx.x;
    const int lane = tid & 31;
    const int wid = tid >> 5;
    const int warp_m = wid & 1;
    const int warp_n = wid >> 1;

    // Per-thread copy coordinates (A: 4 float4, B: 4 float4 per stage)
    const int a_m = tid >> 3;          // base row for i=0 chunk
    const int a_kq = tid & 7;
    const int b_kr = tid >> 5;
    const int b_nq = tid & 31;

    uint32_t As_base = (uint32_t)__cvta_generic_to_shared(As);
    uint32_t Bs_base = (uint32_t)__cvta_generic_to_shared(Bs);

    float acc[4][4][4];
    #pragma unroll
    for (int i = 0; i < 4; i++)
        #pragma unroll
        for (int j = 0; j < 4; j++)
            #pragma unroll
            for (int r = 0; r < 4; r++)
                acc[i][j][r] = 0.0f;

    // issue one stage of copies into slot, for K offset k0 (clamped)
    auto issue = [&](int slot, int k0) {
        uint32_t a_dst = As_base + (uint32_t)(slot * A_STAGE_FLOATS) * 4;
        uint32_t b_dst = Bs_base + (uint32_t)(slot * B_STAGE_FLOATS) * 4;
        const float* a_src = g_x + (size_t)m0 * Kdim + k0;
        const float* b_src = g_W + (size_t)k0 * Ncols + n0;
        #pragma unroll
        for (int i = 0; i < 4; i++) {
            int m = a_m + i * 32;      // rows 0..127 over 4 chunks
            cp_async16(a_dst + (uint32_t)(m * ASTRIDE + a_kq * 4) * 4,
                       a_src + (size_t)m * Kdim + a_kq * 4);
        }
        #pragma unroll
        for (int i = 0; i < 4; i++) {
            int kr = b_kr + i * 8;     // rows 0..31 over 4 chunks
            cp_async16(b_dst + (uint32_t)(kr * BSTRIDE + b_nq * 4) * 4,
                       b_src + (size_t)kr * Ncols + b_nq * 4);
        }
        asm volatile("cp.async.commit_group;\n" ::: "memory");
    };

    // prologue: stages 0 and 1 in flight
    issue(0, 0);
    issue(1, BK);

    #pragma unroll 1
    for (int it = 0; it < NKITER; it++) {
        const int slot = it % STAGES;
        asm volatile("cp.async.wait_group 1;\n" ::: "memory");
        __syncthreads();

        // issue stage it+2 into slot (it+2)%STAGES == (it-1)%STAGES (safe post-barrier)
        {
            int k0 = (it + 2) * BK;
            if (k0 > Kdim - BK) k0 = Kdim - BK;   // redundant tail loads keep pipeline full
            issue((it + 2) % STAGES, k0);
        }

        const float* A_s = As + slot * A_STAGE_FLOATS;
        const float* B_s = Bs + slot * B_STAGE_FLOATS;

        #pragma unroll
        for (int ks = 0; ks < 4; ks++) {
            uint32_t a[4][4], b[4][2];
            const int kk = ks * 8 + (lane & 3);
            #pragma unroll
            for (int mi = 0; mi < 4; mi++) {
                int row = warp_m * 64 + mi * 16 + (lane >> 2);
                a[mi][0] = __float_as_uint(A_s[row * ASTRIDE + kk]);
                a[mi][1] = __float_as_uint(A_s[(row + 8) * ASTRIDE + kk]);
                a[mi][2] = __float_as_uint(A_s[row * ASTRIDE + kk + 4]);
                a[mi][3] = __float_as_uint(A_s[(row + 8) * ASTRIDE + kk + 4]);
            }
            #pragma unroll
            for (int ni = 0; ni < 4; ni++) {
                int col = warp_n * 32 + ni * 8 + (lane >> 2);
                b[ni][0] = __float_as_uint(B_s[kk * BSTRIDE + col]);
                b[ni][1] = __float_as_uint(B_s[(kk + 4) * BSTRIDE + col]);
            }
            #pragma unroll
            for (int mi = 0; mi < 4; mi++)
                #pragma unroll
                for (int ni = 0; ni < 4; ni++)
                    mma_tf32(acc[mi][ni], a[mi], b[ni]);
        }
    }

    // write accumulators
    const int nbase = n0 + warp_n * 32;
    #pragma unroll
    for (int mi = 0; mi < 4; mi++) {
        int row = m0 + warp_m * 64 + mi * 16 + (lane >> 2);
        #pragma unroll
        for (int ni = 0; ni < 4; ni++) {
            int col = nbase + ni * 8 + (lane & 3) * 2;
            float* p = g_C + (size_t)row * Ncols + col;
            *reinterpret_cast<float2*>(p) = make_float2(acc[mi][ni][0], acc[mi][ni][1]);
            *reinterpret_cast<float2*>(p + (size_t)8 * Ncols) =
                make_float2(acc[mi][ni][2], acc[mi][ni][3]);
        }
    }
}

// ---------------------------------------------------------------------------
// Kernel 4: per-token epilogue — rmsnorm(q,k), gamma, RoPE, transpose, repeat
// ---------------------------------------------------------------------------
__global__ __launch_bounds__(256) void epilogue_kernel(
    const float* __restrict__ gq,
    const float* __restrict__ gk,
    float* __restrict__ out)
{
    const int bt = blockIdx.x;       // 0..8191
    const int b = bt >> 12;
    const int t = bt & 4095;
    const float* row = g_C + (size_t)bt * Ncols;
    const int tid = threadIdx.x;

    float2 qv[8], kv2[2];
    float4 vv;
    float ssq_q = 0.0f, ssq_k = 0.0f;
    #pragma unroll
    for (int i = 0; i < 8; i++) {
        int p = tid + i * 256;
        qv[i] = *reinterpret_cast<const float2*>(row + 2 * p);
        ssq_q += qv[i].x * qv[i].x + qv[i].y * qv[i].y;
    }
    #pragma unroll
    for (int i = 0; i < 2; i++) {
        int p = tid + i * 256;
        kv2[i] = *reinterpret_cast<const float2*>(row + 4096 + 2 * p);
        ssq_k += kv2[i].x * kv2[i].x + kv2[i].y * kv2[i].y;
    }
    vv = *reinterpret_cast<const float4*>(row + 5120 + tid * 4);

    __shared__ float redq[256], redk[256];
    redq[tid] = ssq_q;
    redk[tid] = ssq_k;
    __syncthreads();
    #pragma unroll
    for (int s = 128; s > 0; s >>= 1) {
        if (tid < s) {
            redq[tid] += redq[tid + s];
            redk[tid] += redk[tid + s];
        }
        __syncthreads();
    }
    const float rs_q = rsqrtf(redq[0] * (1.0f / 4096.0f) + 1e-5f);
    const float rs_k = rsqrtf(redk[0] * (1.0f / 1024.0f) + 1e-5f);

    const float2* tab = g_tab + t * 64;
    float* outq = out;
    float* outk = out + (size_t)33554432;  // B*H*T*DH
    float* outv = out + (size_t)67108864;

    #pragma unroll
    for (int i = 0; i < 8; i++) {
        int p = tid + i * 256;
        int h = p >> 6;
        int j = p & 63;
        float2 cs = tab[j];
        float x1 = qv[i].x * rs_q * gq[2 * p];
        float x2 = qv[i].y * rs_q * gq[2 * p + 1];
        float2 r = make_float2(x1 * cs.x - x2 * cs.y, x1 * cs.y + x2 * cs.x);
        *reinterpret_cast<float2*>(
            outq + (((size_t)(b * Hh + h) * Tt + t) * DH + 2 * j)) = r;
    }
    #pragma unroll
    for (int i = 0; i < 2; i++) {
        int p = tid + i * 256;
        int kh = p >> 6;
        int j = p & 63;
        float2 cs = tab[j];
        float x1 = kv2[i].x * rs_k * gk[2 * p];
        float x2 = kv2[i].y * rs_k * gk[2 * p + 1];
        float2 r = make_float2(x1 * cs.x - x2 * cs.y, x1 * cs.y + x2 * cs.x);
        #pragma unroll
        for (int rr = 0; rr < 4; rr++) {
            int h = kh * 4 + rr;
            *reinterpret_cast<float2*>(
                outk + (((size_t)(b * Hh + h) * Tt + t) * DH + 2 * j)) = r;
        }
    }
    {
        int d = (tid * 4) & 127;
        int kh = tid >> 5;
        #pragma unroll
        for (int rr = 0; rr < 4; rr++) {
            int h = kh * 4 + rr;
            *reinterpret_cast<float4*>(
                outv + (((size_t)(b * Hh + h) * Tt + t) * DH + d)) = vv;
        }
    }
}

// ---------------------------------------------------------------------------
extern "C" void kernel_launch(void* const* d_in, const int* in_sizes, int n_in,
                              void* d_out, int out_size)
{
    const float* x  = (const float*)d_in[0];
    const float* Wq = (const float*)d_in[1];
    const float* Wk = (const float*)d_in[2];
    const float* Wv = (const float*)d_in[3];
    const float* gq = (const float*)d_in[4];
    const float* gk = (const float*)d_in[5];
    float* out = (float*)d_out;

    static bool attr_set = false;
    if (!attr_set) {
        cudaFuncSetAttribute(gemm_kernel,
                             cudaFuncAttributeMaxDynamicSharedMemorySize, SMEM_BYTES);
        attr_set = true;
    }

    rope_table_kernel<<<(Tt * 64 + 255) / 256, 256>>>();
    convert_x_kernel<<<(int)(((size_t)Mrows * Kdim / 4 + 255) / 256), 256>>>(x);
    convert_w_kernel<<<(int)(((size_t)Kdim * Ncols / 4 + 255) / 256), 256>>>(Wq, Wk, Wv);
    gemm_kernel<<<3072, 256, SMEM_BYTES>>>();
    epilogue_kernel<<<Mrows, 256>>>(gq, gk, out);
}

// round 4
// speedup vs baseline: 2.8465x; 2.1916x over previous
#include <cuda_runtime.h>
#include <cuda_fp16.h>
#include <cstdint>

// Problem constants
#define Bb 2
#define Tt 4096
#define Dd 4096
#define Hh 32
#define HKV 8
#define DH 128
#define Mrows 8192         // B*T
#define Ncols 6144         // D + 2*HKV*DH
#define Kdim 4096

// GEMM tiling (fp16 legacy mma + ldmatrix)
#define BM 128
#define BN 128
#define BK 64
#define NKITER (Kdim / BK)            // 64
#define STAGES 3
#define A_STAGE_BYTES (BM * BK * 2)   // 16384
#define B_STAGE_BYTES (BN * BK * 2)   // 16384
#define SMEM_BYTES (STAGES * (A_STAGE_BYTES + B_STAGE_BYTES))  // 98304

#define MT (Mrows / BM)   // 64
#define NT (Ncols / BN)   // 48
#define GM 16

// Scratch device globals
__device__ float g_C[(size_t)Mrows * Ncols];          // GEMM result (~201 MB)
__device__ __half g_xh[(size_t)Mrows * Kdim];         // fp16 x, [M,K] row-major
__device__ __half g_Wth[(size_t)Ncols * Kdim];        // fp16 W^T, [N,K] row-major
__device__ float2 g_tab[Tt * (DH / 2)];               // RoPE (cos,sin) table

// ---------------------------------------------------------------------------
// PTX helpers
// ---------------------------------------------------------------------------
__device__ __forceinline__ void cp_async16(uint32_t dst, const void* src) {
    asm volatile("cp.async.cg.shared.global [%0], [%1], 16;\n" :: "r"(dst), "l"(src));
}
__device__ __forceinline__ void cp_commit() {
    asm volatile("cp.async.commit_group;\n" ::: "memory");
}
__device__ __forceinline__ void cp_wait1() {
    asm volatile("cp.async.wait_group 1;\n" ::: "memory");
}
__device__ __forceinline__ void ldmatrix_x4(uint32_t r[4], uint32_t addr) {
    asm volatile("ldmatrix.sync.aligned.m8n8.x4.shared.b16 {%0,%1,%2,%3}, [%4];"
                 : "=r"(r[0]), "=r"(r[1]), "=r"(r[2]), "=r"(r[3]) : "r"(addr));
}
__device__ __forceinline__ void mma_f16(float c[4], const uint32_t a[4], const uint32_t b[2]) {
    asm volatile(
        "mma.sync.aligned.m16n8k16.row.col.f32.f16.f16.f32 "
        "{%0,%1,%2,%3}, {%4,%5,%6,%7}, {%8,%9}, {%0,%1,%2,%3};"
        : "+f"(c[0]), "+f"(c[1]), "+f"(c[2]), "+f"(c[3])
        : "r"(a[0]), "r"(a[1]), "r"(a[2]), "r"(a[3]), "r"(b[0]), "r"(b[1]));
}
__device__ __forceinline__ uint32_t swz128(uint32_t off) {
    return off ^ ((off >> 3) & 0x70);
}

// ---------------------------------------------------------------------------
// Kernel 1: RoPE cos/sin table
// ---------------------------------------------------------------------------
__global__ void rope_table_kernel() {
    int idx = blockIdx.x * blockDim.x + threadIdx.x;
    if (idx >= Tt * 64) return;
    int t = idx >> 6;
    int j = idx & 63;
    double inv = exp2(-((double)(2 * j)) * (1.0 / 128.0) * 13.287712379549449);
    double a = (double)t * inv;
    double red = remainder(a, 6.283185307179586477);
    float s, c;
    sincosf((float)red, &s, &c);
    g_tab[idx] = make_float2(c, s);
}

// ---------------------------------------------------------------------------
// Kernel 2a: convert x -> fp16
// ---------------------------------------------------------------------------
__global__ void convert_x_kernel(const float* __restrict__ x) {
    size_t i = (size_t)blockIdx.x * blockDim.x + threadIdx.x;   // float4 index
    const size_t N4 = (size_t)Mrows * Kdim / 4;
    if (i >= N4) return;
    float4 v = reinterpret_cast<const float4*>(x)[i];
    __half2 h0 = make_half2(__float2half_rn(v.x), __float2half_rn(v.y));
    __half2 h1 = make_half2(__float2half_rn(v.z), __float2half_rn(v.w));
    reinterpret_cast<__half2*>(g_xh)[2 * i]     = h0;
    reinterpret_cast<__half2*>(g_xh)[2 * i + 1] = h1;
}

// ---------------------------------------------------------------------------
// Kernel 2b: transpose + convert [Wq|Wk|Wv] -> fp16 g_Wth[n][k]
// grid (192, 128), block (32, 8)
// ---------------------------------------------------------------------------
__global__ void convert_w_kernel(const float* __restrict__ Wq,
                                 const float* __restrict__ Wk,
                                 const float* __restrict__ Wv) {
    __shared__ __half tile[32][34];
    const int n0 = blockIdx.x * 32;
    const int k0 = blockIdx.y * 32;
    #pragma unroll
    for (int i = 0; i < 4; i++) {
        int k = k0 + threadIdx.y + i * 8;
        int n = n0 + threadIdx.x;
        float v;
        if (n < 4096)       v = Wq[(size_t)k * 4096 + n];
        else if (n < 5120)  v = Wk[(size_t)k * 1024 + (n - 4096)];
        else                v = Wv[(size_t)k * 1024 + (n - 5120)];
        tile[threadIdx.y + i * 8][threadIdx.x] = __float2half_rn(v);
    }
    __syncthreads();
    #pragma unroll
    for (int i = 0; i < 4; i++) {
        int n = n0 + threadIdx.y + i * 8;
        int k = k0 + threadIdx.x;
        g_Wth[(size_t)n * Kdim + k] = tile[threadIdx.x][threadIdx.y + i * 8];
    }
}

// ---------------------------------------------------------------------------
// Kernel 3: fp16 GEMM  C[8192,6144] = g_xh @ g_Wth^T   (ldmatrix + HMMA)
// 3072 CTAs (64 M x 48 N, GROUP_M=16), 256 thr = 8 warps (2M x 4N), warp 64x32
// ---------------------------------------------------------------------------
__global__ __launch_bounds__(256, 2) void gemm_kernel() {
    extern __shared__ char smem[];
    const uint32_t smem_base = (uint32_t)__cvta_generic_to_shared(smem);
    const uint32_t a_base = smem_base;                          // 3 x 16KB
    const uint32_t b_base = smem_base + STAGES * A_STAGE_BYTES; // 3 x 16KB

    int gid = blockIdx.x;
    int group = gid / (GM * NT);
    int rem = gid % (GM * NT);
    const int mt = group * GM + (rem % GM);
    const int nt = rem / GM;
    const int m0 = mt * BM;
    const int n0 = nt * BN;

    const int tid = threadIdx.x;
    const int lane = tid & 31;
    const int wid = tid >> 5;
    const int warp_m = wid & 1;   // 0..1, 64 rows
    const int warp_n = wid >> 1;  // 0..3, 32 cols

    float acc[4][4][4];
    #pragma unroll
    for (int i = 0; i < 4; i++)
        #pragma unroll
        for (int j = 0; j < 4; j++)
            #pragma unroll
            for (int r = 0; r < 4; r++)
                acc[i][j][r] = 0.0f;

    // copy coordinates: 1024 16B-chunks per operand per stage, 4 per thread
    const int c_row = tid >> 1;            // base row for chunks (two kq per thread pair)
    auto issue = [&](int ktile, int slot) {
        const int k0 = ktile * BK;
        const uint32_t a_dst = a_base + slot * A_STAGE_BYTES;
        const uint32_t b_dst = b_base + slot * B_STAGE_BYTES;
        const __half* a_src = g_xh + (size_t)m0 * Kdim + k0;
        const __half* b_src = g_Wth + (size_t)n0 * Kdim + k0;
        #pragma unroll
        for (int i = 0; i < 4; i++) {
            int idx = tid + i * 256;       // 0..1023
            int row = idx >> 3;            // 0..127
            int kq = idx & 7;              // 16B chunk within 128B row
            cp_async16(a_dst + swz128(row * 128 + kq * 16),
                       a_src + (size_t)row * Kdim + kq * 8);
        }
        #pragma unroll
        for (int i = 0; i < 4; i++) {
            int idx = tid + i * 256;
            int row = idx >> 3;
            int kq = idx & 7;
            cp_async16(b_dst + swz128(row * 128 + kq * 16),
                       b_src + (size_t)row * Kdim + kq * 8);
        }
        cp_commit();
    };

    issue(0, 0);
    issue(1, 1);

    // precomputed ldmatrix lane addressing offsets
    const int a_row = warp_m * 64 + (lane & 15);       // + mi*16
    const int a_ch  = lane >> 4;                       // + ks*2
    const int b_row = warp_n * 32 + (lane & 7) + ((lane >> 4) << 3);  // + ng*16
    const int b_ch  = (lane >> 3) & 1;                 // + ks*2

    #pragma unroll 1
    for (int it = 0; it < NKITER; it++) {
        const int slot = it % STAGES;
        cp_wait1();
        __syncthreads();

        {
            int lt = it + 2;
            if (lt > NKITER - 1) lt = NKITER - 1;
            issue(lt, (it + 2) % STAGES);
        }

        const uint32_t A_s = a_base + slot * A_STAGE_BYTES;
        const uint32_t B_s = b_base + slot * B_STAGE_BYTES;

        #pragma unroll
        for (int ks = 0; ks < 4; ks++) {
            uint32_t a[4][4], b[2][4];
            #pragma unroll
            for (int mi = 0; mi < 4; mi++)
                ldmatrix_x4(a[mi], A_s + swz128((a_row + mi * 16) * 128 +
                                                (ks * 2 + a_ch) * 16));
            #pragma unroll
            for (int ng = 0; ng < 2; ng++)
                ldmatrix_x4(b[ng], B_s + swz128((b_row + ng * 16) * 128 +
                                                (ks * 2 + b_ch) * 16));
            #pragma unroll
            for (int mi = 0; mi < 4; mi++) {
                #pragma unroll
                for (int ng = 0; ng < 2; ng++) {
                    mma_f16(acc[mi][ng * 2],     a[mi], &b[ng][0]);
                    mma_f16(acc[mi][ng * 2 + 1], a[mi], &b[ng][2]);
                }
            }
        }
    }

    // write accumulators to scratch C
    const int nbase = n0 + warp_n * 32;
    #pragma unroll
    for (int mi = 0; mi < 4; mi++) {
        int row = m0 + warp_m * 64 + mi * 16 + (lane >> 2);
        #pragma unroll
        for (int ni = 0; ni < 4; ni++) {
            int col = nbase + ni * 8 + (lane & 3) * 2;
            float* p = g_C + (size_t)row * Ncols + col;
            *reinterpret_cast<float2*>(p) = make_float2(acc[mi][ni][0], acc[mi][ni][1]);
            *reinterpret_cast<float2*>(p + (size_t)8 * Ncols) =
                make_float2(acc[mi][ni][2], acc[mi][ni][3]);
        }
    }
}

// ---------------------------------------------------------------------------
// Kernel 4: per-token epilogue — rmsnorm(q,k), gamma, RoPE, transpose, repeat
// ---------------------------------------------------------------------------
__global__ __launch_bounds__(256) void epilogue_kernel(
    const float* __restrict__ gq,
    const float* __restrict__ gk,
    float* __restrict__ out)
{
    const int bt = blockIdx.x;
    const int b = bt >> 12;
    const int t = bt & 4095;
    const float* row = g_C + (size_t)bt * Ncols;
    const int tid = threadIdx.x;

    float2 qv[8], kv2[2];
    float4 vv;
    float ssq_q = 0.0f, ssq_k = 0.0f;
    #pragma unroll
    for (int i = 0; i < 8; i++) {
        int p = tid + i * 256;
        qv[i] = *reinterpret_cast<const float2*>(row + 2 * p);
        ssq_q += qv[i].x * qv[i].x + qv[i].y * qv[i].y;
    }
    #pragma unroll
    for (int i = 0; i < 2; i++) {
        int p = tid + i * 256;
        kv2[i] = *reinterpret_cast<const float2*>(row + 4096 + 2 * p);
        ssq_k += kv2[i].x * kv2[i].x + kv2[i].y * kv2[i].y;
    }
    vv = *reinterpret_cast<const float4*>(row + 5120 + tid * 4);

    __shared__ float redq[256], redk[256];
    redq[tid] = ssq_q;
    redk[tid] = ssq_k;
    __syncthreads();
    #pragma unroll
    for (int s = 128; s > 0; s >>= 1) {
        if (tid < s) {
            redq[tid] += redq[tid + s];
            redk[tid] += redk[tid + s];
        }
        __syncthreads();
    }
    const float rs_q = rsqrtf(redq[0] * (1.0f / 4096.0f) + 1e-5f);
    const float rs_k = rsqrtf(redk[0] * (1.0f / 1024.0f) + 1e-5f);

    const float2* tab = g_tab + t * 64;
    float* outq = out;
    float* outk = out + (size_t)33554432;
    float* outv = out + (size_t)67108864;

    #pragma unroll
    for (int i = 0; i < 8; i++) {
        int p = tid + i * 256;
        int h = p >> 6;
        int j = p & 63;
        float2 cs = tab[j];
        float x1 = qv[i].x * rs_q * gq[2 * p];
        float x2 = qv[i].y * rs_q * gq[2 * p + 1];
        float2 r = make_float2(x1 * cs.x - x2 * cs.y, x1 * cs.y + x2 * cs.x);
        *reinterpret_cast<float2*>(
            outq + (((size_t)(b * Hh + h) * Tt + t) * DH + 2 * j)) = r;
    }
    #pragma unroll
    for (int i = 0; i < 2; i++) {
        int p = tid + i * 256;
        int kh = p >> 6;
        int j = p & 63;
        float2 cs = tab[j];
        float x1 = kv2[i].x * rs_k * gk[2 * p];
        float x2 = kv2[i].y * rs_k * gk[2 * p + 1];
        float2 r = make_float2(x1 * cs.x - x2 * cs.y, x1 * cs.y + x2 * cs.x);
        #pragma unroll
        for (int rr = 0; rr < 4; rr++) {
            int h = kh * 4 + rr;
            *reinterpret_cast<float2*>(
                outk + (((size_t)(b * Hh + h) * Tt + t) * DH + 2 * j)) = r;
        }
    }
    {
        int d = (tid * 4) & 127;
        int kh = tid >> 5;
        #pragma unroll
        for (int rr = 0; rr < 4; rr++) {
            int h = kh * 4 + rr;
            *reinterpret_cast<float4*>(
                outv + (((size_t)(b * Hh + h) * Tt + t) * DH + d)) = vv;
        }
    }
}

// ---------------------------------------------------------------------------
extern "C" void kernel_launch(void* const* d_in, const int* in_sizes, int n_in,
                              void* d_out, int out_size)
{
    const float* x  = (const float*)d_in[0];
    const float* Wq = (const float*)d_in[1];
    const float* Wk = (const float*)d_in[2];
    const float* Wv = (const float*)d_in[3];
    const float* gq = (const float*)d_in[4];
    const float* gk = (const float*)d_in[5];
    float* out = (float*)d_out;

    cudaFuncSetAttribute(gemm_kernel,
                         cudaFuncAttributeMaxDynamicSharedMemorySize, SMEM_BYTES);

    rope_table_kernel<<<(Tt * 64 + 255) / 256, 256>>>();
    convert_x_kernel<<<(int)(((size_t)Mrows * Kdim / 4 + 255) / 256), 256>>>(x);
    convert_w_kernel<<<dim3(Ncols / 32, Kdim / 32), dim3(32, 8)>>>(Wq, Wk, Wv);
    gemm_kernel<<<MT * NT, 256, SMEM_BYTES>>>();
    epilogue_kernel<<<Mrows, 256>>>(gq, gk, out);
}